// round 7
// baseline (speedup 1.0000x reference)
#include <cuda_runtime.h>
#include <cstdint>

#define B_DIM 256
#define R_DIM 2048
#define M_DIM 65536
#define L_DIM 64
#define H_DIM 4
#define BH    1024
#define KSPLIT 8

// ---- persistent device scratch (no runtime allocation allowed) ----
__device__ float g_kpart[KSPLIT][B_DIM][256];  // keys GEMM K-split partials
__device__ float g_q[BH][L_DIM];               // folded queries: beta*key/||key||
__device__ float g_part[BH][128];              // per-(row, m-block) partial sums
__device__ float g_inv[BH];                    // 1 / rowsum

__device__ __forceinline__ uint32_t f2tf32(float x) {
    uint32_t u;
    asm("cvt.rna.tf32.f32 %0, %1;" : "=r"(u) : "f"(x));
    return u;
}

__device__ __forceinline__ void mma_tf32(float c[4], const uint32_t a[4],
                                         uint32_t b0, uint32_t b1) {
    asm volatile(
        "mma.sync.aligned.m16n8k8.row.col.f32.tf32.tf32.f32 "
        "{%0,%1,%2,%3}, {%4,%5,%6,%7}, {%8,%9}, {%0,%1,%2,%3};\n"
        : "+f"(c[0]), "+f"(c[1]), "+f"(c[2]), "+f"(c[3])
        : "r"(a[0]), "r"(a[1]), "r"(a[2]), "r"(a[3]), "r"(b0), "r"(b1));
}

// ============================================================================
// A1: keys GEMM partials = rs[256,2048] @ Wk^T, K-split by 8.
// ============================================================================
__global__ __launch_bounds__(256) void a1_keys_gemm(const float* __restrict__ rs,
                                                    const float* __restrict__ Wk) {
    __shared__ float rs_s[32][68];
    __shared__ float wk_s[32][68];
    const int tid = threadIdx.x;
    const int tx = tid & 15, ty = tid >> 4;
    const int b0 = blockIdx.x * 64, o0 = blockIdx.y * 64;
    const int k0 = blockIdx.z * (R_DIM / KSPLIT);

    float acc[4][4] = {};
    for (int kc = 0; kc < R_DIM / KSPLIT; kc += 32) {
        #pragma unroll
        for (int f = 0; f < 2; f++) {
            int id  = tid + f * 256;
            int row = id >> 3;
            int kk  = (id & 7) * 4;
            const float4 v = *(const float4*)(rs + (size_t)(b0 + row) * R_DIM + k0 + kc + kk);
            rs_s[kk + 0][row] = v.x; rs_s[kk + 1][row] = v.y;
            rs_s[kk + 2][row] = v.z; rs_s[kk + 3][row] = v.w;
            const float4 w = *(const float4*)(Wk + (size_t)(o0 + row) * R_DIM + k0 + kc + kk);
            wk_s[kk + 0][row] = w.x; wk_s[kk + 1][row] = w.y;
            wk_s[kk + 2][row] = w.z; wk_s[kk + 3][row] = w.w;
        }
        __syncthreads();
        #pragma unroll
        for (int kk = 0; kk < 32; kk++) {
            const float4 a = *(const float4*)&rs_s[kk][ty * 4];
            const float4 w = *(const float4*)&wk_s[kk][tx * 4];
            acc[0][0] += a.x * w.x; acc[0][1] += a.x * w.y; acc[0][2] += a.x * w.z; acc[0][3] += a.x * w.w;
            acc[1][0] += a.y * w.x; acc[1][1] += a.y * w.y; acc[1][2] += a.y * w.z; acc[1][3] += a.y * w.w;
            acc[2][0] += a.z * w.x; acc[2][1] += a.z * w.y; acc[2][2] += a.z * w.z; acc[2][3] += a.z * w.w;
            acc[3][0] += a.w * w.x; acc[3][1] += a.w * w.y; acc[3][2] += a.w * w.z; acc[3][3] += a.w * w.w;
        }
        __syncthreads();
    }
    #pragma unroll
    for (int i = 0; i < 4; i++) {
        float4 v = make_float4(acc[i][0], acc[i][1], acc[i][2], acc[i][3]);
        *(float4*)&g_kpart[blockIdx.z][b0 + ty * 4 + i][o0 + tx * 4] = v;
    }
}

// ============================================================================
// A2: fold into q = beta * key / ||key||.
// ============================================================================
__global__ __launch_bounds__(64) void a2_finalize(const float* __restrict__ rs,
                                                  const float* __restrict__ bk,
                                                  const float* __restrict__ Wb,
                                                  const float* __restrict__ bb) {
    const int bh = blockIdx.x;
    const int b = bh >> 2, h = bh & 3;
    const int l = threadIdx.x;

    float key = bk[h * 64 + l];
    #pragma unroll
    for (int s = 0; s < KSPLIT; s++) key += g_kpart[s][b][h * 64 + l];

    float bp = 0.f;
    for (int k = l; k < R_DIM; k += 64)
        bp += rs[(size_t)b * R_DIM + k] * Wb[(size_t)h * R_DIM + k];

    __shared__ float red[64];
    red[l] = bp;
    __syncthreads();
    #pragma unroll
    for (int off = 32; off > 0; off >>= 1) {
        if (l < off) red[l] += red[l + off];
        __syncthreads();
    }
    const float beta = fmaxf(red[0] + bb[h], 0.f);
    __syncthreads();

    red[l] = key * key;
    __syncthreads();
    #pragma unroll
    for (int off = 32; off > 0; off >>= 1) {
        if (l < off) red[l] += red[l + off];
        __syncthreads();
    }
    const float ssq = red[0];
    const float scale = beta / sqrtf(ssq);
    g_q[bh][l] = key * scale;
}

// ============================================================================
// Fused passes v2: A-frags hoisted to registers; pair-packed m_s for LDS.64.
//   pass1 (WRITE=false): per-(row, mb) partial sums -> g_part (transposed)
//   pass2 (WRITE=true) : out = exp(logit) * g_inv[row]
// grid (128 mb x 8 bhg), 256 thr; block tile 128bh x (4 x 128m); warp 32bh x 64m
// ============================================================================
#define MS_STRIDE 72
#define SMEM_FLOATS (128 * MS_STRIDE + 256)
#define SMEM_BYTES  (SMEM_FLOATS * 4)

template <bool WRITE>
__global__ __launch_bounds__(256) void pass_kernel(const float* __restrict__ mem,
                                                   float* __restrict__ out) {
    extern __shared__ float smem[];
    float* m_s = smem;                       // [128][72] pair-packed tf32 bits
    float* red = smem + 128 * MS_STRIDE;     // [256]

    const int tid = threadIdx.x;
    const int lane = tid & 31, warp = tid >> 5;
    const int wbh = warp >> 1, wm = warp & 1;
    const int g = lane >> 2, qd = lane & 3;
    const int mb = blockIdx.x, bhg = blockIdx.y;
    const int row0 = bhg * 128;

    // ---- hoist A fragments for the whole block (q constant across tiles) ----
    // A[i][ks][s]: s0=q[r][k], s1=q[r+8][k], s2=q[r][k+4], s3=q[r+8][k+4]
    uint32_t A[2][8][4];
    {
        const int rb = row0 + wbh * 32 + g;
        #pragma unroll
        for (int i = 0; i < 2; i++) {
            #pragma unroll
            for (int ks = 0; ks < 8; ks++) {
                const int c = ks * 8 + qd;
                A[i][ks][0] = f2tf32(g_q[rb + i * 16][c]);
                A[i][ks][1] = f2tf32(g_q[rb + i * 16 + 8][c]);
                A[i][ks][2] = f2tf32(g_q[rb + i * 16][c + 4]);
                A[i][ks][3] = f2tf32(g_q[rb + i * 16 + 8][c + 4]);
            }
        }
    }

    float inv[2][2];
    if (WRITE) {
        #pragma unroll
        for (int i = 0; i < 2; i++)
            #pragma unroll
            for (int hh = 0; hh < 2; hh++)
                inv[i][hh] = g_inv[row0 + wbh * 32 + i * 16 + hh * 8 + g];
    }
    float rsum[2][2] = {{0.f, 0.f}, {0.f, 0.f}};

    for (int t = 0; t < 4; t++) {
        const int m0 = (mb * 4 + t) * 128;
        // fill m tile, pair-packed: col c -> pos = (c>>3)*8 + (c&3)*2 + ((c>>2)&1)
        #pragma unroll
        for (int f = 0; f < 8; f++) {
            int id = tid + f * 256;
            int r = id >> 4, c4 = (id & 15) * 4;
            float4 v = *(const float4*)(mem + (size_t)(m0 + r) * L_DIM + c4);
            const int ks = c4 >> 3, hi = (c4 >> 2) & 1;
            float* dst = &m_s[r * MS_STRIDE + ks * 8 + hi];
            dst[0] = __uint_as_float(f2tf32(v.x));
            dst[2] = __uint_as_float(f2tf32(v.y));
            dst[4] = __uint_as_float(f2tf32(v.z));
            dst[6] = __uint_as_float(f2tf32(v.w));
        }
        __syncthreads();

        float acc[2][8][4] = {};
        #pragma unroll
        for (int ks = 0; ks < 8; ks++) {
            #pragma unroll
            for (int j = 0; j < 8; j++) {
                const int n = wm * 64 + j * 8 + g;
                const float2 b = *(const float2*)&m_s[n * MS_STRIDE + ks * 8 + qd * 2];
                const uint32_t b0 = __float_as_uint(b.x);
                const uint32_t b1 = __float_as_uint(b.y);
                mma_tf32(acc[0][j], A[0][ks], b0, b1);
                mma_tf32(acc[1][j], A[1][ks], b0, b1);
            }
        }
        __syncthreads();  // all warps done reading m_s before next fill

        #pragma unroll
        for (int i = 0; i < 2; i++) {
            #pragma unroll
            for (int j = 0; j < 8; j++) {
                const float e0 = __expf(acc[i][j][0]);
                const float e1 = __expf(acc[i][j][1]);
                const float e2 = __expf(acc[i][j][2]);
                const float e3 = __expf(acc[i][j][3]);
                if (WRITE) {
                    const int row = row0 + wbh * 32 + i * 16 + g;
                    const int col = m0 + wm * 64 + j * 8 + 2 * qd;
                    float2 p0 = make_float2(e0 * inv[i][0], e1 * inv[i][0]);
                    float2 p1 = make_float2(e2 * inv[i][1], e3 * inv[i][1]);
                    *(float2*)(out + (size_t)row * M_DIM + col) = p0;
                    *(float2*)(out + (size_t)(row + 8) * M_DIM + col) = p1;
                } else {
                    rsum[i][0] += e0 + e1;
                    rsum[i][1] += e2 + e3;
                }
            }
        }
    }

    if (!WRITE) {
        #pragma unroll
        for (int i = 0; i < 2; i++) {
            #pragma unroll
            for (int hh = 0; hh < 2; hh++) {
                float v = rsum[i][hh];
                v += __shfl_xor_sync(0xffffffffu, v, 1);
                v += __shfl_xor_sync(0xffffffffu, v, 2);
                if (qd == 0)
                    red[wm * 128 + wbh * 32 + i * 16 + hh * 8 + g] = v;
            }
        }
        __syncthreads();
        if (tid < 128)
            g_part[row0 + tid][mb] = red[tid] + red[128 + tid];
    }
}

// ============================================================================
// deterministic rowsum reduce -> inverse. warp per row, float4 coalesced.
// ============================================================================
__global__ __launch_bounds__(256) void reduce_inv_kernel() {
    const int warp = threadIdx.x >> 5, lane = threadIdx.x & 31;
    const int row = blockIdx.x * 8 + warp;  // 128 blocks x 8 warps
    const float4 v = *(const float4*)&g_part[row][lane * 4];
    float s = (v.x + v.y) + (v.z + v.w);
    #pragma unroll
    for (int off = 16; off > 0; off >>= 1)
        s += __shfl_xor_sync(0xffffffffu, s, off);
    if (lane == 0) g_inv[row] = 1.0f / s;
}

// ============================================================================
extern "C" void kernel_launch(void* const* d_in, const int* in_sizes, int n_in,
                              void* d_out, int out_size) {
    const float* rs  = (const float*)d_in[0];
    const float* mem = (const float*)d_in[1];
    const float* Wk  = (const float*)d_in[2];
    const float* bk  = (const float*)d_in[3];
    const float* Wb  = (const float*)d_in[4];
    const float* bb  = (const float*)d_in[5];
    float* out = (float*)d_out;

    cudaFuncSetAttribute(pass_kernel<false>, cudaFuncAttributeMaxDynamicSharedMemorySize, SMEM_BYTES);
    cudaFuncSetAttribute(pass_kernel<true>,  cudaFuncAttributeMaxDynamicSharedMemorySize, SMEM_BYTES);

    a1_keys_gemm<<<dim3(4, 4, KSPLIT), 256>>>(rs, Wk);
    a2_finalize<<<BH, 64>>>(rs, bk, Wb, bb);
    pass_kernel<false><<<dim3(128, 8), 256, SMEM_BYTES>>>(mem, out);
    reduce_inv_kernel<<<128, 256>>>();
    pass_kernel<true><<<dim3(128, 8), 256, SMEM_BYTES>>>(mem, out);
}

// round 10
// speedup vs baseline: 1.2696x; 1.2696x over previous
#include <cuda_runtime.h>
#include <cstdint>

#define B_DIM 256
#define R_DIM 2048
#define M_DIM 65536
#define L_DIM 64
#define H_DIM 4
#define BH    1024
#define KSPLIT 8
#define UNITS_TOTAL 4096   // 8 bh-groups x 512 m-tiles

// ---- persistent device scratch ----
__device__ float g_kpart[KSPLIT][B_DIM][256];
__device__ float g_q[BH][L_DIM];
__device__ float g_part[BH][512];     // per-(row, m-tile) partial sums (2 MB)
__device__ float g_inv[BH];
__device__ unsigned int g_ctr1, g_ctr2;

__device__ __forceinline__ uint32_t f2tf32(float x) {
    uint32_t u;
    asm("cvt.rna.tf32.f32 %0, %1;" : "=r"(u) : "f"(x));
    return u;
}

__device__ __forceinline__ void mma_tf32(float c[4], const uint32_t a[4],
                                         uint32_t b0, uint32_t b1) {
    asm volatile(
        "mma.sync.aligned.m16n8k8.row.col.f32.tf32.tf32.f32 "
        "{%0,%1,%2,%3}, {%4,%5,%6,%7}, {%8,%9}, {%0,%1,%2,%3};\n"
        : "+f"(c[0]), "+f"(c[1]), "+f"(c[2]), "+f"(c[3])
        : "r"(a[0]), "r"(a[1]), "r"(a[2]), "r"(a[3]), "r"(b0), "r"(b1));
}

// ============================================================================
// A1: keys GEMM partials = rs[256,2048] @ Wk^T, K-split by 8. Also resets ctrs.
// ============================================================================
__global__ __launch_bounds__(256) void a1_keys_gemm(const float* __restrict__ rs,
                                                    const float* __restrict__ Wk) {
    if (blockIdx.x == 0 && blockIdx.y == 0 && blockIdx.z == 0 && threadIdx.x == 0) {
        g_ctr1 = 0u;
        g_ctr2 = 0u;
    }
    __shared__ float rs_s[32][68];
    __shared__ float wk_s[32][68];
    const int tid = threadIdx.x;
    const int tx = tid & 15, ty = tid >> 4;
    const int b0 = blockIdx.x * 64, o0 = blockIdx.y * 64;
    const int k0 = blockIdx.z * (R_DIM / KSPLIT);

    float acc[4][4] = {};
    for (int kc = 0; kc < R_DIM / KSPLIT; kc += 32) {
        #pragma unroll
        for (int f = 0; f < 2; f++) {
            int id  = tid + f * 256;
            int row = id >> 3;
            int kk  = (id & 7) * 4;
            const float4 v = *(const float4*)(rs + (size_t)(b0 + row) * R_DIM + k0 + kc + kk);
            rs_s[kk + 0][row] = v.x; rs_s[kk + 1][row] = v.y;
            rs_s[kk + 2][row] = v.z; rs_s[kk + 3][row] = v.w;
            const float4 w = *(const float4*)(Wk + (size_t)(o0 + row) * R_DIM + k0 + kc + kk);
            wk_s[kk + 0][row] = w.x; wk_s[kk + 1][row] = w.y;
            wk_s[kk + 2][row] = w.z; wk_s[kk + 3][row] = w.w;
        }
        __syncthreads();
        #pragma unroll
        for (int kk = 0; kk < 32; kk++) {
            const float4 a = *(const float4*)&rs_s[kk][ty * 4];
            const float4 w = *(const float4*)&wk_s[kk][tx * 4];
            acc[0][0] += a.x * w.x; acc[0][1] += a.x * w.y; acc[0][2] += a.x * w.z; acc[0][3] += a.x * w.w;
            acc[1][0] += a.y * w.x; acc[1][1] += a.y * w.y; acc[1][2] += a.y * w.z; acc[1][3] += a.y * w.w;
            acc[2][0] += a.z * w.x; acc[2][1] += a.z * w.y; acc[2][2] += a.z * w.z; acc[2][3] += a.z * w.w;
            acc[3][0] += a.w * w.x; acc[3][1] += a.w * w.y; acc[3][2] += a.w * w.z; acc[3][3] += a.w * w.w;
        }
        __syncthreads();
    }
    #pragma unroll
    for (int i = 0; i < 4; i++) {
        float4 v = make_float4(acc[i][0], acc[i][1], acc[i][2], acc[i][3]);
        *(float4*)&g_kpart[blockIdx.z][b0 + ty * 4 + i][o0 + tx * 4] = v;
    }
}

// ============================================================================
// A2: fold into q = beta * key / ||key||  (unchanged)
// ============================================================================
__global__ __launch_bounds__(64) void a2_finalize(const float* __restrict__ rs,
                                                  const float* __restrict__ bk,
                                                  const float* __restrict__ Wb,
                                                  const float* __restrict__ bb) {
    const int bh = blockIdx.x;
    const int b = bh >> 2, h = bh & 3;
    const int l = threadIdx.x;

    float key = bk[h * 64 + l];
    #pragma unroll
    for (int s = 0; s < KSPLIT; s++) key += g_kpart[s][b][h * 64 + l];

    float bp = 0.f;
    for (int k = l; k < R_DIM; k += 64)
        bp += rs[(size_t)b * R_DIM + k] * Wb[(size_t)h * R_DIM + k];

    __shared__ float red[64];
    red[l] = bp;
    __syncthreads();
    #pragma unroll
    for (int off = 32; off > 0; off >>= 1) {
        if (l < off) red[l] += red[l + off];
        __syncthreads();
    }
    const float beta = fmaxf(red[0] + bb[h], 0.f);
    __syncthreads();

    red[l] = key * key;
    __syncthreads();
    #pragma unroll
    for (int off = 32; off > 0; off >>= 1) {
        if (l < off) red[l] += red[l + off];
        __syncthreads();
    }
    const float scale = beta / sqrtf(red[0]);
    g_q[bh][l] = key * scale;
}

// ============================================================================
// Persistent fused passes (round-2 math, work-stolen tiles).
// Unit id in [0,4096): bhg = id>>9 (q tile of 128 rows), mt = id&511 (128 m).
// 296 CTAs (2/SM), shared-ticket dynamic scheduling -> no wave quantization.
//   pass1 (WRITE=false): per-(row, mt) exp-sums -> g_part
//   pass2 (WRITE=true) : out = exp(logit) * g_inv[row]
// ============================================================================
#define QS_STRIDE 68
#define SMEM_FLOATS (2 * 128 * QS_STRIDE + 256)
#define SMEM_BYTES  (SMEM_FLOATS * 4)

template <bool WRITE>
__global__ __launch_bounds__(256, 2) void pass_kernel(const float* __restrict__ mem,
                                                      float* __restrict__ out,
                                                      unsigned int* __restrict__ ctr) {
    extern __shared__ float smem[];
    float* q_s = smem;                       // [128][68] tf32 bits
    float* m_s = smem + 128 * QS_STRIDE;     // [128][68] tf32 bits
    float* red = smem + 2 * 128 * QS_STRIDE; // [256]
    __shared__ int s_id;

    const int tid = threadIdx.x;
    const int lane = tid & 31, warp = tid >> 5;
    const int wbh = warp >> 1, wm = warp & 1;
    const int g = lane >> 2, qd = lane & 3;

    int cached_bhg = -1;

    for (;;) {
        if (tid == 0) s_id = (int)atomicAdd(ctr, 1u);
        __syncthreads();            // broadcast id; all prior m_s/red reads done
        const int id = s_id;
        if (id >= UNITS_TOTAL) break;
        const int bhg = id >> 9, mt = id & 511;
        const int row0 = bhg << 7;
        const int m0 = mt * 128;

        if (bhg != cached_bhg) {
            cached_bhg = bhg;
            #pragma unroll
            for (int f = 0; f < 8; f++) {
                int i = tid + f * 256;
                int r = i >> 4, c4 = (i & 15) * 4;
                float4 v = *(const float4*)&g_q[row0 + r][c4];
                float4 w;
                w.x = __uint_as_float(f2tf32(v.x)); w.y = __uint_as_float(f2tf32(v.y));
                w.z = __uint_as_float(f2tf32(v.z)); w.w = __uint_as_float(f2tf32(v.w));
                *(float4*)&q_s[r * QS_STRIDE + c4] = w;
            }
        }
        #pragma unroll
        for (int f = 0; f < 8; f++) {
            int i = tid + f * 256;
            int r = i >> 4, c4 = (i & 15) * 4;
            float4 v = *(const float4*)(mem + (size_t)(m0 + r) * L_DIM + c4);
            float4 w;
            w.x = __uint_as_float(f2tf32(v.x)); w.y = __uint_as_float(f2tf32(v.y));
            w.z = __uint_as_float(f2tf32(v.z)); w.w = __uint_as_float(f2tf32(v.w));
            *(float4*)&m_s[r * QS_STRIDE + c4] = w;
        }
        __syncthreads();

        float acc[2][8][4] = {};
        #pragma unroll
        for (int ks = 0; ks < 8; ks++) {
            const int kb = ks * 8;
            uint32_t a[2][4];
            #pragma unroll
            for (int i = 0; i < 2; i++) {
                const int r = wbh * 32 + i * 16 + g;
                a[i][0] = __float_as_uint(q_s[r * QS_STRIDE + kb + qd]);
                a[i][1] = __float_as_uint(q_s[(r + 8) * QS_STRIDE + kb + qd]);
                a[i][2] = __float_as_uint(q_s[r * QS_STRIDE + kb + qd + 4]);
                a[i][3] = __float_as_uint(q_s[(r + 8) * QS_STRIDE + kb + qd + 4]);
            }
            #pragma unroll
            for (int j = 0; j < 8; j++) {
                const int n = wm * 64 + j * 8 + g;
                const uint32_t b0 = __float_as_uint(m_s[n * QS_STRIDE + kb + qd]);
                const uint32_t b1 = __float_as_uint(m_s[n * QS_STRIDE + kb + qd + 4]);
                mma_tf32(acc[0][j], a[0], b0, b1);
                mma_tf32(acc[1][j], a[1], b0, b1);
            }
        }

        float rsum[2][2] = {{0.f, 0.f}, {0.f, 0.f}};
        float inv[2][2];
        if (WRITE) {
            #pragma unroll
            for (int i = 0; i < 2; i++)
                #pragma unroll
                for (int hh = 0; hh < 2; hh++)
                    inv[i][hh] = g_inv[row0 + wbh * 32 + i * 16 + hh * 8 + g];
        }
        #pragma unroll
        for (int i = 0; i < 2; i++) {
            #pragma unroll
            for (int j = 0; j < 8; j++) {
                const float e0 = __expf(acc[i][j][0]);
                const float e1 = __expf(acc[i][j][1]);
                const float e2 = __expf(acc[i][j][2]);
                const float e3 = __expf(acc[i][j][3]);
                if (WRITE) {
                    const int row = row0 + wbh * 32 + i * 16 + g;
                    const int col = m0 + wm * 64 + j * 8 + 2 * qd;
                    float2 p0 = make_float2(e0 * inv[i][0], e1 * inv[i][0]);
                    float2 p1 = make_float2(e2 * inv[i][1], e3 * inv[i][1]);
                    *(float2*)(out + (size_t)row * M_DIM + col) = p0;
                    *(float2*)(out + (size_t)(row + 8) * M_DIM + col) = p1;
                } else {
                    rsum[i][0] += e0 + e1;
                    rsum[i][1] += e2 + e3;
                }
            }
        }

        if (!WRITE) {
            #pragma unroll
            for (int i = 0; i < 2; i++) {
                #pragma unroll
                for (int hh = 0; hh < 2; hh++) {
                    float v = rsum[i][hh];
                    v += __shfl_xor_sync(0xffffffffu, v, 1);
                    v += __shfl_xor_sync(0xffffffffu, v, 2);
                    if (qd == 0)
                        red[wm * 128 + wbh * 32 + i * 16 + hh * 8 + g] = v;
                }
            }
            __syncthreads();
            if (tid < 128)
                g_part[row0 + tid][mt] = red[tid] + red[128 + tid];
        }
    }
}

// ============================================================================
// deterministic rowsum reduce -> inverse. warp per row, coalesced float4.
// ============================================================================
__global__ __launch_bounds__(256) void reduce_inv_kernel() {
    const int warp = threadIdx.x >> 5, lane = threadIdx.x & 31;
    const int row = blockIdx.x * 8 + warp;  // 128 blocks x 8 warps
    float s = 0.f;
    #pragma unroll
    for (int i = 0; i < 4; i++) {
        const float4 v = *(const float4*)&g_part[row][i * 128 + lane * 4];
        s += (v.x + v.y) + (v.z + v.w);
    }
    #pragma unroll
    for (int off = 16; off > 0; off >>= 1)
        s += __shfl_xor_sync(0xffffffffu, s, off);
    if (lane == 0) g_inv[row] = 1.0f / s;
}

// ============================================================================
extern "C" void kernel_launch(void* const* d_in, const int* in_sizes, int n_in,
                              void* d_out, int out_size) {
    const float* rs  = (const float*)d_in[0];
    const float* mem = (const float*)d_in[1];
    const float* Wk  = (const float*)d_in[2];
    const float* bk  = (const float*)d_in[3];
    const float* Wb  = (const float*)d_in[4];
    const float* bb  = (const float*)d_in[5];
    float* out = (float*)d_out;

    unsigned int* c1;
    unsigned int* c2;
    cudaGetSymbolAddress((void**)&c1, g_ctr1);
    cudaGetSymbolAddress((void**)&c2, g_ctr2);

    cudaFuncSetAttribute(pass_kernel<false>, cudaFuncAttributeMaxDynamicSharedMemorySize, SMEM_BYTES);
    cudaFuncSetAttribute(pass_kernel<true>,  cudaFuncAttributeMaxDynamicSharedMemorySize, SMEM_BYTES);

    a1_keys_gemm<<<dim3(4, 4, KSPLIT), 256>>>(rs, Wk);
    a2_finalize<<<BH, 64>>>(rs, bk, Wb, bb);
    pass_kernel<false><<<296, 256, SMEM_BYTES>>>(mem, out, c1);
    reduce_inv_kernel<<<128, 256>>>();
    pass_kernel<true><<<296, 256, SMEM_BYTES>>>(mem, out, c2);
}